// round 14
// baseline (speedup 1.0000x reference)
#include <cuda_runtime.h>
#include <cuda_bf16.h>
#include <math.h>

#define B_ 8
#define T_ 256
#define S_ 1024
#define V_ 32000
#define L_ 2
#define GS_ 4096
#define GRID_REC 128
#define EPS_ 1e-5f

// ---------------- static device scratch (no runtime allocation) ----------
__device__ float d_xproj[(size_t)T_ * B_ * GS_];            // [T][B][4S]
__device__ float d_H0[(size_t)T_ * B_ * S_];                // [T][B][S]
__device__ float d_H1[(size_t)T_ * B_ * S_];
__device__ float d_red[2 * B_ * GRID_REC * 2];              // LN partials
__device__ unsigned d_bar[64];                              // [0]=count, [32]=gen

// bf16 hi/lo split scratch
__device__ __nv_bfloat16 d_Wxh[(size_t)L_ * GS_ * S_];
__device__ __nv_bfloat16 d_Wxl[(size_t)L_ * GS_ * S_];
__device__ __nv_bfloat16 d_Wouth[(size_t)V_ * S_];
__device__ __nv_bfloat16 d_Woutl[(size_t)V_ * S_];
__device__ __nv_bfloat16 d_Ah[(size_t)T_ * B_ * S_];
__device__ __nv_bfloat16 d_Al[(size_t)T_ * B_ * S_];

// ---------------- fp32 -> bf16 hi/lo split helpers -----------------------
__device__ __forceinline__ void split4(float4 v, unsigned& h0, unsigned& h1,
                                       unsigned& l0, unsigned& l1) {
    __nv_bfloat16 a = __float2bfloat16(v.x), b = __float2bfloat16(v.y);
    __nv_bfloat16 c = __float2bfloat16(v.z), d = __float2bfloat16(v.w);
    __nv_bfloat162 hA; hA.x = a; hA.y = b;
    __nv_bfloat162 hB; hB.x = c; hB.y = d;
    h0 = *reinterpret_cast<unsigned*>(&hA);
    h1 = *reinterpret_cast<unsigned*>(&hB);
    __nv_bfloat162 lA, lB;
    lA.x = __float2bfloat16(v.x - __bfloat162float(a));
    lA.y = __float2bfloat16(v.y - __bfloat162float(b));
    lB.x = __float2bfloat16(v.z - __bfloat162float(c));
    lB.y = __float2bfloat16(v.w - __bfloat162float(d));
    l0 = *reinterpret_cast<unsigned*>(&lA);
    l1 = *reinterpret_cast<unsigned*>(&lB);
}

__global__ void cvt_split_k(const float* __restrict__ s,
                            __nv_bfloat16* __restrict__ h,
                            __nv_bfloat16* __restrict__ l, int n4) {
    int i = blockIdx.x * blockDim.x + threadIdx.x;
    if (i >= n4) return;
    float4 v = __ldg((const float4*)s + i);
    uint2 hp, lp;
    split4(v, hp.x, hp.y, lp.x, lp.y);
    ((uint2*)h)[i] = hp;
    ((uint2*)l)[i] = lp;
}

// fused split of Wx (both layers) and Wout in ONE launch
__global__ void cvt_splitW_k(const float* __restrict__ Wx,
                             const float* __restrict__ Wout,
                             __nv_bfloat16* __restrict__ Wxh, __nv_bfloat16* __restrict__ Wxl,
                             __nv_bfloat16* __restrict__ Wouth, __nv_bfloat16* __restrict__ Woutl) {
    const int nA = L_ * GS_ * S_ / 4;
    const int nB = V_ * S_ / 4;
    int i = blockIdx.x * blockDim.x + threadIdx.x;
    if (i < nA) {
        float4 v = __ldg((const float4*)Wx + i);
        uint2 hp, lp;
        split4(v, hp.x, hp.y, lp.x, lp.y);
        ((uint2*)Wxh)[i] = hp;
        ((uint2*)Wxl)[i] = lp;
    } else if (i < nA + nB) {
        int j = i - nA;
        float4 v = __ldg((const float4*)Wout + j);
        uint2 hp, lp;
        split4(v, hp.x, hp.y, lp.x, lp.y);
        ((uint2*)Wouth)[j] = hp;
        ((uint2*)Woutl)[j] = lp;
    }
}

// gather + split; block 0 also (re)initializes the grid barrier
__global__ void cvt_gather_k(const float* __restrict__ emb, const int* __restrict__ tok,
                             __nv_bfloat16* __restrict__ h, __nv_bfloat16* __restrict__ l,
                             unsigned* __restrict__ bar) {
    if (blockIdx.x == 0 && threadIdx.x == 0) { bar[0] = 0u; bar[32] = 0u; }
    int i = blockIdx.x * blockDim.x + threadIdx.x;
    int row = i >> 8, col4 = i & 255;
    int tk = __ldg(&tok[(row & 7) * T_ + (row >> 3)]);
    float4 v = __ldg((const float4*)(emb + (size_t)tk * S_) + col4);
    uint2 hp, lp;
    split4(v, hp.x, hp.y, lp.x, lp.y);
    ((uint2*)h)[i] = hp;
    ((uint2*)l)[i] = lp;
}

// ---------------- mma / ldsm / cp.async primitives ------------------------
__device__ __forceinline__ void cpa16(unsigned dst, const void* src) {
    asm volatile("cp.async.cg.shared.global [%0], [%1], 16;\n" :: "r"(dst), "l"(src));
}
__device__ __forceinline__ void ldsm4(unsigned& r0, unsigned& r1, unsigned& r2,
                                      unsigned& r3, unsigned addr) {
    asm volatile("ldmatrix.sync.aligned.m8n8.x4.shared.b16 {%0,%1,%2,%3}, [%4];\n"
                 : "=r"(r0), "=r"(r1), "=r"(r2), "=r"(r3) : "r"(addr));
}
__device__ __forceinline__ void ldsm2(unsigned& r0, unsigned& r1, unsigned addr) {
    asm volatile("ldmatrix.sync.aligned.m8n8.x2.shared.b16 {%0,%1}, [%2];\n"
                 : "=r"(r0), "=r"(r1) : "r"(addr));
}
__device__ __forceinline__ void mma16816(float* c, const unsigned* a, const unsigned* b) {
    asm volatile(
        "mma.sync.aligned.m16n8k16.row.col.f32.bf16.bf16.f32 "
        "{%0,%1,%2,%3}, {%4,%5,%6,%7}, {%8,%9}, {%0,%1,%2,%3};\n"
        : "+f"(c[0]), "+f"(c[1]), "+f"(c[2]), "+f"(c[3])
        : "r"(a[0]), "r"(a[1]), "r"(a[2]), "r"(a[3]), "r"(b[0]), "r"(b[1]));
}

// ============== bf16-split tensor-core GEMM: 512 threads, 16 warps ========
#define STAGE_BYTES 65536u
#define GEMM_SMEM   (3 * 65536)

__global__ void __launch_bounds__(512)
gemm_tc(int M, int N, int K,
        const __nv_bfloat16* __restrict__ Ah, const __nv_bfloat16* __restrict__ Al,
        const __nv_bfloat16* __restrict__ Bh, const __nv_bfloat16* __restrict__ Bl,
        const float* __restrict__ bias, float* __restrict__ C, int mode)
{
    extern __shared__ char smx[];
    const unsigned sbase = (unsigned)__cvta_generic_to_shared(smx);
    const int tid = threadIdx.x;
    const int m0 = blockIdx.x * 128;
    const int n0 = blockIdx.y * 128;

    const int row  = tid & 255;
    const int half = tid >> 8;
    const int lr   = row & 127;
    const int isB  = row >> 7;
    const __nv_bfloat16* gh = isB ? (Bh + (size_t)(n0 + lr) * K)
                                  : (Ah + (size_t)(m0 + lr) * K);
    const __nv_bfloat16* gl = isB ? (Bl + (size_t)(n0 + lr) * K)
                                  : (Al + (size_t)(m0 + lr) * K);
    const unsigned matH = isB ? 32768u : 0u;
    const unsigned matL = matH + 16384u;
    const unsigned dstRow = (unsigned)lr * 128u;
    const unsigned swL = (unsigned)(lr & 7) * 16u;
    const int c0 = half * 4;

    const int wid = tid >> 5, lane = tid & 31;
    const int warp_m = wid & 3, warp_n = wid >> 2;
    const int m_base = warp_m * 32, n_base = warp_n * 32;
    const unsigned aswz = (unsigned)(lane & 7) * 16u;
    const unsigned arow = (unsigned)(m_base + (lane & 7) + ((lane >> 3) & 1) * 8);
    const unsigned acol = (unsigned)(lane >> 4);
    const unsigned brow = (unsigned)(n_base + (lane & 7) + ((lane >> 4) & 1) * 8);
    const unsigned bcol = (unsigned)((lane >> 3) & 1);

    float acc[2][4][4];
    #pragma unroll
    for (int i = 0; i < 2; ++i)
        #pragma unroll
        for (int j = 0; j < 4; ++j)
            #pragma unroll
            for (int k = 0; k < 4; ++k) acc[i][j][k] = 0.f;

    const int KT = K >> 6;

    #pragma unroll
    for (int s = 0; s < 2; ++s) {
        unsigned sb = sbase + (unsigned)s * STAGE_BYTES + dstRow;
        const __nv_bfloat16* ph = gh + s * 64;
        const __nv_bfloat16* pl = gl + s * 64;
        #pragma unroll
        for (int c = 0; c < 4; ++c) {
            unsigned off = ((unsigned)((c0 + c) * 16)) ^ swL;
            cpa16(sb + matH + off, ph + (c0 + c) * 8);
            cpa16(sb + matL + off, pl + (c0 + c) * 8);
        }
        asm volatile("cp.async.commit_group;\n");
    }

    int cur = 0;
    for (int kt = 0; kt < KT; ++kt) {
        if (kt < KT - 1) asm volatile("cp.async.wait_group 1;\n");
        else             asm volatile("cp.async.wait_group 0;\n");
        __syncthreads();

        const unsigned sb = sbase + (unsigned)cur * STAGE_BYTES;

        #pragma unroll
        for (int kc = 0; kc < 4; ++kc) {
            unsigned ah[2][4], al[2][4], bh[4][2], bl[4][2];
            const unsigned ac = ((2u * kc + acol) * 16u) ^ aswz;
            const unsigned bc = ((2u * kc + bcol) * 16u) ^ aswz;
            #pragma unroll
            for (int p = 0; p < 2; ++p) {
                unsigned addr = sb + 32768u + (brow + p * 16u) * 128u + bc;
                ldsm4(bh[2*p][0], bh[2*p][1], bh[2*p+1][0], bh[2*p+1][1], addr);
                ldsm4(bl[2*p][0], bl[2*p][1], bl[2*p+1][0], bl[2*p+1][1], addr + 16384u);
            }
            #pragma unroll
            for (int fm = 0; fm < 2; ++fm) {
                unsigned addr = sb + (arow + fm * 16u) * 128u + ac;
                ldsm4(ah[fm][0], ah[fm][1], ah[fm][2], ah[fm][3], addr);
                ldsm4(al[fm][0], al[fm][1], al[fm][2], al[fm][3], addr + 16384u);
            }
            #pragma unroll
            for (int fm = 0; fm < 2; ++fm)
                #pragma unroll
                for (int fn = 0; fn < 4; ++fn)
                    mma16816(acc[fm][fn], ah[fm], bh[fn]);
            #pragma unroll
            for (int fm = 0; fm < 2; ++fm)
                #pragma unroll
                for (int fn = 0; fn < 4; ++fn)
                    mma16816(acc[fm][fn], ah[fm], bl[fn]);
            #pragma unroll
            for (int fm = 0; fm < 2; ++fm)
                #pragma unroll
                for (int fn = 0; fn < 4; ++fn)
                    mma16816(acc[fm][fn], al[fm], bh[fn]);
        }

        if (kt + 2 < KT) {
            int s = kt + 2;
            int slot = s - (s / 3) * 3;
            unsigned sb2 = sbase + (unsigned)slot * STAGE_BYTES + dstRow;
            const __nv_bfloat16* ph = gh + s * 64;
            const __nv_bfloat16* pl = gl + s * 64;
            #pragma unroll
            for (int c = 0; c < 4; ++c) {
                unsigned off = ((unsigned)((c0 + c) * 16)) ^ swL;
                cpa16(sb2 + matH + off, ph + (c0 + c) * 8);
                cpa16(sb2 + matL + off, pl + (c0 + c) * 8);
            }
        }
        asm volatile("cp.async.commit_group;\n");

        if (++cur == 3) cur = 0;
    }

    const int g = lane >> 2, q = lane & 3;
    #pragma unroll
    for (int fm = 0; fm < 2; ++fm) {
        int row0 = m0 + m_base + fm * 16 + g;
        int row1 = row0 + 8;
        float *p0, *p1;
        if (mode == 0) {
            p0 = C + (size_t)row0 * N;
            p1 = C + (size_t)row1 * N;
        } else {
            p0 = C + (size_t)(row0 & 7) * ((size_t)T_ * V_) + (size_t)(row0 >> 3) * V_;
            p1 = C + (size_t)(row1 & 7) * ((size_t)T_ * V_) + (size_t)(row1 >> 3) * V_;
        }
        #pragma unroll
        for (int fn = 0; fn < 4; ++fn) {
            int col = n0 + n_base + fn * 8 + q * 2;
            float b0 = 0.f, b1 = 0.f;
            if (bias) { b0 = __ldg(&bias[col]); b1 = __ldg(&bias[col + 1]); }
            float2 v0 = make_float2(acc[fm][fn][0] + b0, acc[fm][fn][1] + b1);
            float2 v1 = make_float2(acc[fm][fn][2] + b0, acc[fm][fn][3] + b1);
            *(float2*)(p0 + col) = v0;
            *(float2*)(p1 + col) = v1;
        }
    }
}

// ---------------- persistent recurrence: 512 threads, fused reduction -----
#define WHH_OFF 0u
#define WHL_OFF 65536u
#define HH_OFF  131072u
#define HL_OFF  147456u
#define PART_OFF 163840u          // 16 warps x 2 mt x 128 floats = 16 KB
#define FP_OFF   180224u
#define REC_BYTES (180224 + 320 * 4)

// single-counter generation barrier + nanosleep poll backoff.
__device__ __forceinline__ void grid_barrier(unsigned* bar) {
    __syncthreads();
    if (threadIdx.x == 0) {
        unsigned g;
        asm volatile("ld.acquire.gpu.global.u32 %0, [%1];" : "=r"(g) : "l"(bar + 32));
        unsigned old;
        asm volatile("atom.release.gpu.global.add.u32 %0, [%1], %2;"
                     : "=r"(old) : "l"(bar), "r"(1u));
        if (old == GRID_REC - 1) {
            asm volatile("st.relaxed.gpu.global.u32 [%0], %1;" :: "l"(bar), "r"(0u));
            asm volatile("red.release.gpu.global.add.u32 [%0], %1;" :: "l"(bar + 32), "r"(1u));
        } else {
            unsigned cur2;
            asm volatile("ld.acquire.gpu.global.u32 %0, [%1];" : "=r"(cur2) : "l"(bar + 32));
            while (cur2 == g) {
                asm volatile("nanosleep.u32 64;");
                asm volatile("ld.acquire.gpu.global.u32 %0, [%1];" : "=r"(cur2) : "l"(bar + 32));
            }
        }
    }
    __syncthreads();
}

__device__ __forceinline__ float sigmf(float x) { return 1.f / (1.f + expf(-x)); }

__global__ void __launch_bounds__(512, 1)
lstm_rec(const float* __restrict__ xproj,
         const float* __restrict__ Wh,
         const float* __restrict__ gamma, const float* __restrict__ beta,
         float* __restrict__ H,
         float* __restrict__ hfin, float* __restrict__ cfin,
         float* __restrict__ red, unsigned* __restrict__ bar)
{
    extern __shared__ char smem[];
    const unsigned sb = (unsigned)__cvta_generic_to_shared(smem);
    float* fp     = (float*)(smem + FP_OFF);
    float* craw   = fp;            // 64
    float* hbuf   = fp + 64;       // 64
    float* gmb    = fp + 128;      // 16
    float* stat   = fp + 144;      // 16
    float* lnpart = fp + 160;      // 128
    float* partf  = (float*)(smem + PART_OFF);  // 4096 floats

    const int tid = threadIdx.x;
    const int blk = blockIdx.x;
    const int s0  = blk * 8;
    const int wid = tid >> 5, lane = tid & 31;

    {   // load Wh -> smem bf16 hi/lo planes; 32 rows x 16 threads each
        int r = tid >> 4, s = tid & 15;
        int g = r >> 3, u = r & 7;
        const float4* src = (const float4*)(Wh + (size_t)(g * S_ + s0 + u) * S_);
        unsigned rowb = (unsigned)r * 2048u;
        unsigned sw = (unsigned)(r & 7) * 16u;
        #pragma unroll 4
        for (int jj = 0; jj < 8; ++jj) {
            int cj = s * 8 + jj;
            float4 v1 = __ldg(src + cj * 2);
            float4 v2 = __ldg(src + cj * 2 + 1);
            uint4 hi, lo;
            split4(v1, hi.x, hi.y, lo.x, lo.y);
            split4(v2, hi.z, hi.w, lo.z, lo.w);
            unsigned off = rowb + (((unsigned)cj * 16u) ^ sw);
            *(uint4*)(smem + WHH_OFF + off) = hi;
            *(uint4*)(smem + WHL_OFF + off) = lo;
        }
    }
    if (tid < 8)  { gmb[tid] = __ldg(&gamma[s0 + tid]); gmb[8 + tid] = __ldg(&beta[s0 + tid]); }
    __syncthreads();

    const int uu = tid >> 3, bb = tid & 7;     // gate coords (tid<64)

    // mma fragment address components
    const unsigned arl = (unsigned)((lane & 7) + ((lane >> 3) & 1) * 8);
    const unsigned asw = (unsigned)(lane & 7) * 16u;
    const unsigned akh = (unsigned)(lane >> 4) * 16u;
    const unsigned brl = (unsigned)(lane & 7);
    const unsigned bkh = (unsigned)((lane >> 3) & 1) * 16u;
    const unsigned bsw = brl * 16u;

    // h-convert role: warp pair per batch row
    const int hb   = wid >> 1;       // batch row 0..7
    const int hsel = wid & 1;        // which half of the row

    for (int t = 0; t < T_; ++t) {
        float xpi = 0.f, xpf = 0.f, xpo = 0.f, xpg = 0.f;
        if (tid < 64) {
            const float* xp = xproj + (size_t)(t * B_ + bb) * GS_ + s0 + uu;
            xpi = __ldg(xp + 0 * S_); xpf = __ldg(xp + 1 * S_);
            xpo = __ldg(xp + 2 * S_); xpg = __ldg(xp + 3 * S_);
        }

        if (t > 0) {
            {   // load h(t-1), convert, store planes: 2 chunks per thread
                const float* Hrow = H + (size_t)(t - 1) * (B_ * S_) + (size_t)hb * S_;
                unsigned rowb = (unsigned)hb * 2048u;
                unsigned sw = (unsigned)hb * 16u;
                #pragma unroll
                for (int j = 0; j < 2; ++j) {
                    int chunk = hsel * 64 + j * 32 + lane;
                    float4 v1 = __ldcg((const float4*)(Hrow + chunk * 8));
                    float4 v2 = __ldcg((const float4*)(Hrow + chunk * 8 + 4));
                    uint4 hi, lo;
                    split4(v1, hi.x, hi.y, lo.x, lo.y);
                    split4(v2, hi.z, hi.w, lo.z, lo.w);
                    unsigned off = rowb + ((((unsigned)chunk) * 16u) ^ sw);
                    *(uint4*)(smem + HH_OFF + off) = hi;
                    *(uint4*)(smem + HL_OFF + off) = lo;
                }
            }
            if (tid < 64) {   // LN partial gather for step t-1
                int par = (t - 1) & 1;
                const float* rp = red + (size_t)par * B_ * GRID_REC * 2;
                int b = tid >> 3, seg = tid & 7;
                float s1 = 0.f, s2 = 0.f;
                #pragma unroll
                for (int q = 0; q < 16; ++q) {
                    float2 v = __ldcg((const float2*)(rp + ((size_t)b * GRID_REC + seg * 16 + q) * 2));
                    s1 += v.x; s2 += v.y;
                }
                lnpart[tid * 2] = s1; lnpart[tid * 2 + 1] = s2;
            }
            __syncthreads();

            if (tid < 8) {   // finalize LN stats
                float s1 = 0.f, s2 = 0.f;
                #pragma unroll
                for (int seg = 0; seg < 8; ++seg) {
                    s1 += lnpart[(tid * 8 + seg) * 2];
                    s2 += lnpart[(tid * 8 + seg) * 2 + 1];
                }
                float mu = s1 * (1.f / (float)S_);
                float var = s2 * (1.f / (float)S_) - mu * mu;
                stat[tid] = mu; stat[8 + tid] = rsqrtf(var + EPS_);
            }

            // ---- tensor-core dot: warp w covers k-chunks {w, w+16, w+32, w+48}
            float acc[2][4];
            #pragma unroll
            for (int mt = 0; mt < 2; ++mt)
                #pragma unroll
                for (int r = 0; r < 4; ++r) acc[mt][r] = 0.f;

            #pragma unroll
            for (int i = 0; i < 4; ++i) {
                unsigned c32 = (unsigned)(wid + i * 16) * 32u;
                unsigned bh[2], bl[2];
                unsigned boff = brl * 2048u + ((c32 + bkh) ^ bsw);
                ldsm2(bh[0], bh[1], sb + HH_OFF + boff);
                ldsm2(bl[0], bl[1], sb + HL_OFF + boff);
                unsigned ah0[4], al0[4], ah1[4], al1[4];
                unsigned ak = (c32 + akh) ^ asw;
                unsigned a0 = arl * 2048u + ak;
                unsigned a1 = (arl + 16u) * 2048u + ak;
                ldsm4(ah0[0], ah0[1], ah0[2], ah0[3], sb + WHH_OFF + a0);
                ldsm4(al0[0], al0[1], al0[2], al0[3], sb + WHL_OFF + a0);
                ldsm4(ah1[0], ah1[1], ah1[2], ah1[3], sb + WHH_OFF + a1);
                ldsm4(al1[0], al1[1], al1[2], al1[3], sb + WHL_OFF + a1);
                mma16816(acc[0], ah0, bh);
                mma16816(acc[1], ah1, bh);
                mma16816(acc[0], ah0, bl);
                mma16816(acc[1], ah1, bl);
                mma16816(acc[0], al0, bh);
                mma16816(acc[1], al1, bh);
            }
            #pragma unroll
            for (int mt = 0; mt < 2; ++mt) {
                float4* pd = (float4*)partf + (wid * 2 + mt) * 32 + lane;
                *pd = make_float4(acc[mt][0], acc[mt][1], acc[mt][2], acc[mt][3]);
            }
            __syncthreads();
        }

        if (tid < 64) {
            float cn = 0.f;
            float gi = 0.f, gf = 0.f, go2 = 0.f, gg2 = 0.f;
            if (t > 0) {
                cn = (craw[tid] - stat[bb]) * stat[8 + bb] * gmb[uu] + gmb[8 + uu];
                // fused cross-warp reduction: 4 gate cols, 16 warps each
                float gs[4];
                #pragma unroll
                for (int g4 = 0; g4 < 4; ++g4) {
                    int col = g4 * 8 + uu;
                    int mt = col >> 4, rr = col & 15;
                    int gg = rr & 7, half = rr >> 3;
                    int reg = half * 2 + (bb & 1);
                    int ln = gg * 4 + (bb >> 1);
                    float v = 0.f;
                    #pragma unroll
                    for (int w2 = 0; w2 < 16; ++w2)
                        v += partf[(w2 * 2 + mt) * 128 + ln * 4 + reg];
                    gs[g4] = v;
                }
                gi = gs[0]; gf = gs[1]; go2 = gs[2]; gg2 = gs[3];
            }
            float pi = xpi + gi;
            float pf = xpf + gf;
            float po = xpo + go2;
            float pg = xpg + gg2;
            float ig = sigmf(pi), fg = sigmf(pf), og = sigmf(po), g2 = tanhf(pg);
            float cr = fg * cn + ig * g2;
            float hh = og * tanhf(cr);
            craw[tid] = cr;
            hbuf[tid] = hh;
            H[(size_t)t * (B_ * S_) + bb * S_ + s0 + uu] = hh;
        }
        __syncthreads();

        if (tid < 8) {   // per-block LN partials for batch b=tid
            float s1 = 0.f, s2 = 0.f;
            #pragma unroll
            for (int u = 0; u < 8; ++u) { float v = craw[u * 8 + tid]; s1 += v; s2 += v * v; }
            float2* rp = (float2*)(red + ((size_t)(t & 1) * B_ + tid) * (GRID_REC * 2) + blk * 2);
            *rp = make_float2(s1, s2);
        }

        grid_barrier(bar);
    }

    // final LN for t = T-1 -> cfin; hfin from hbuf
    {
        int par = (T_ - 1) & 1;
        const float* rp = red + (size_t)par * B_ * GRID_REC * 2;
        if (tid < 64) {
            int b = tid >> 3, seg = tid & 7;
            float s1 = 0.f, s2 = 0.f;
            #pragma unroll
            for (int q = 0; q < 16; ++q) {
                float2 v = __ldcg((const float2*)(rp + ((size_t)b * GRID_REC + seg * 16 + q) * 2));
                s1 += v.x; s2 += v.y;
            }
            lnpart[tid * 2] = s1; lnpart[tid * 2 + 1] = s2;
        }
        __syncthreads();
        if (tid < 8) {
            float s1 = 0.f, s2 = 0.f;
            #pragma unroll
            for (int seg = 0; seg < 8; ++seg) {
                s1 += lnpart[(tid * 8 + seg) * 2];
                s2 += lnpart[(tid * 8 + seg) * 2 + 1];
            }
            float mu = s1 * (1.f / (float)S_);
            float var = s2 * (1.f / (float)S_) - mu * mu;
            stat[tid] = mu; stat[8 + tid] = rsqrtf(var + EPS_);
        }
        __syncthreads();
        if (tid < 64) {
            float cn = (craw[tid] - stat[bb]) * stat[8 + bb] * gmb[uu] + gmb[8 + uu];
            cfin[bb * S_ + s0 + uu] = cn;
            hfin[bb * S_ + s0 + uu] = hbuf[tid];
        }
    }
}

// ---------------- host launcher -------------------------------------------
extern "C" void kernel_launch(void* const* d_in, const int* in_sizes, int n_in,
                              void* d_out, int out_size)
{
    (void)in_sizes; (void)n_in; (void)out_size;
    const int*   x     = (const int*)d_in[0];
    const float* emb   = (const float*)d_in[1];
    const float* Wx    = (const float*)d_in[2];
    const float* Wh    = (const float*)d_in[3];
    const float* gamma = (const float*)d_in[4];
    const float* beta  = (const float*)d_in[5];
    const float* Wout  = (const float*)d_in[6];
    const float* bout  = (const float*)d_in[7];
    float* out = (float*)d_out;

    float *xproj, *H0, *H1, *red;
    unsigned* bar;
    __nv_bfloat16 *Wxh, *Wxl, *Wouth, *Woutl, *Ah, *Al;
    cudaGetSymbolAddress((void**)&xproj, d_xproj);
    cudaGetSymbolAddress((void**)&H0,    d_H0);
    cudaGetSymbolAddress((void**)&H1,    d_H1);
    cudaGetSymbolAddress((void**)&red,   d_red);
    cudaGetSymbolAddress((void**)&bar,   d_bar);
    cudaGetSymbolAddress((void**)&Wxh,   d_Wxh);
    cudaGetSymbolAddress((void**)&Wxl,   d_Wxl);
    cudaGetSymbolAddress((void**)&Wouth, d_Wouth);
    cudaGetSymbolAddress((void**)&Woutl, d_Woutl);
    cudaGetSymbolAddress((void**)&Ah,    d_Ah);
    cudaGetSymbolAddress((void**)&Al,    d_Al);

    cudaFuncSetAttribute(lstm_rec, cudaFuncAttributeMaxDynamicSharedMemorySize, REC_BYTES);
    cudaFuncSetAttribute(gemm_tc, cudaFuncAttributeMaxDynamicSharedMemorySize, GEMM_SMEM);

    float* h_out = out + (size_t)B_ * T_ * V_;
    float* c_out = h_out + (size_t)L_ * B_ * S_;

    const size_t wstride = (size_t)GS_ * S_;
    const int nW4 = L_ * GS_ * S_ / 4 + V_ * S_ / 4;

    // launch 1: gather (re-inits barrier)
    cvt_gather_k<<<(T_ * B_ * S_ / 4 + 255) / 256, 256>>>(emb, x, Ah, Al, bar);
    // launch 2: fused Wx + Wout split
    cvt_splitW_k<<<(nW4 + 255) / 256, 256>>>(Wx, Wout, Wxh, Wxl, Wouth, Woutl);
    // launch 3: layer-0 input projection
    gemm_tc<<<dim3((T_ * B_) / 128, GS_ / 128), 512, GEMM_SMEM>>>(
        T_ * B_, GS_, S_, Ah, Al, Wxh, Wxl, nullptr, xproj, 0);
    // launch 4: layer-0 recurrence
    lstm_rec<<<GRID_REC, 512, REC_BYTES>>>(
        xproj, Wh, gamma, beta, H0, h_out, c_out, red, bar);
    // launch 5: split H0
    cvt_split_k<<<(T_ * B_ * S_ / 4 + 255) / 256, 256>>>(H0, Ah, Al, T_ * B_ * S_ / 4);
    // launch 6: layer-1 input projection
    gemm_tc<<<dim3((T_ * B_) / 128, GS_ / 128), 512, GEMM_SMEM>>>(
        T_ * B_, GS_, S_, Ah, Al, Wxh + wstride, Wxl + wstride, nullptr, xproj, 0);
    // launch 7: layer-1 recurrence
    lstm_rec<<<GRID_REC, 512, REC_BYTES>>>(
        xproj, Wh + wstride, gamma + S_, beta + S_, H1,
        h_out + (size_t)B_ * S_, c_out + (size_t)B_ * S_, red, bar);
    // launch 8: split H1
    cvt_split_k<<<(T_ * B_ * S_ / 4 + 255) / 256, 256>>>(H1, Ah, Al, T_ * B_ * S_ / 4);
    // launch 9: logits
    gemm_tc<<<dim3((T_ * B_) / 128, V_ / 128), 512, GEMM_SMEM>>>(
        T_ * B_, V_, S_, Ah, Al, Wouth, Woutl, bout, out, 1);
}

// round 16
// speedup vs baseline: 1.1756x; 1.1756x over previous
#include <cuda_runtime.h>
#include <cuda_bf16.h>
#include <math.h>

#define B_ 8
#define T_ 256
#define S_ 1024
#define V_ 32000
#define L_ 2
#define GS_ 4096
#define GRID_REC 128
#define EPS_ 1e-5f
#define KT_ 16            // K stages (K=1024 / 64)

// ---------------- static device scratch (no runtime allocation) ----------
__device__ float d_xproj[(size_t)T_ * B_ * GS_];            // [T][B][4S]
__device__ float d_H0[(size_t)T_ * B_ * S_];                // [T][B][S]
__device__ float d_H1[(size_t)T_ * B_ * S_];
__device__ float d_red[2 * B_ * GRID_REC * 2];              // LN partials
__device__ unsigned d_bar[64];                              // [0]=count, [32]=gen

// bf16 hi/lo split scratch, TILED layout: [tile][stage] x 16KB swizzled blocks
__device__ __align__(128) __nv_bfloat16 d_Wxh[(size_t)L_ * GS_ * S_];
__device__ __align__(128) __nv_bfloat16 d_Wxl[(size_t)L_ * GS_ * S_];
__device__ __align__(128) __nv_bfloat16 d_Wouth[(size_t)V_ * S_];
__device__ __align__(128) __nv_bfloat16 d_Woutl[(size_t)V_ * S_];
__device__ __align__(128) __nv_bfloat16 d_Ah[(size_t)T_ * B_ * S_];
__device__ __align__(128) __nv_bfloat16 d_Al[(size_t)T_ * B_ * S_];

// ---------------- fp32 -> bf16 hi/lo split helpers -----------------------
__device__ __forceinline__ void split4(float4 v, unsigned& h0, unsigned& h1,
                                       unsigned& l0, unsigned& l1) {
    __nv_bfloat16 a = __float2bfloat16(v.x), b = __float2bfloat16(v.y);
    __nv_bfloat16 c = __float2bfloat16(v.z), d = __float2bfloat16(v.w);
    __nv_bfloat162 hA; hA.x = a; hA.y = b;
    __nv_bfloat162 hB; hB.x = c; hB.y = d;
    h0 = *reinterpret_cast<unsigned*>(&hA);
    h1 = *reinterpret_cast<unsigned*>(&hB);
    __nv_bfloat162 lA, lB;
    lA.x = __float2bfloat16(v.x - __bfloat162float(a));
    lA.y = __float2bfloat16(v.y - __bfloat162float(b));
    lB.x = __float2bfloat16(v.z - __bfloat162float(c));
    lB.y = __float2bfloat16(v.w - __bfloat162float(d));
    l0 = *reinterpret_cast<unsigned*>(&lA);
    l1 = *reinterpret_cast<unsigned*>(&lB);
}

// tiled-layout chunk address: byte offset of 16B chunk (tile,stage,row,chunk)
__device__ __forceinline__ size_t tiled_off(int tile, int stage, int row, int chunk) {
    return ((size_t)(tile * KT_ + stage)) * 16384 + (size_t)row * 128
         + (unsigned)((chunk * 16) ^ ((row & 7) * 16));
}

// generic fp32 [R,1024] row-major -> tiled hi/lo planes
__global__ void cvt_tiled_k(const float* __restrict__ src,
                            __nv_bfloat16* __restrict__ h,
                            __nv_bfloat16* __restrict__ l, int nchunks) {
    int i = blockIdx.x * blockDim.x + threadIdx.x;
    if (i >= nchunks) return;
    int chunk = i & 7;
    int row   = (i >> 3) & 127;
    int stage = (i >> 10) & 15;
    int tile  = i >> 14;
    int grow  = tile * 128 + row;
    int k     = stage * 64 + chunk * 8;
    const float4* s4 = (const float4*)(src + (size_t)grow * S_ + k);
    float4 v1 = __ldg(s4), v2 = __ldg(s4 + 1);
    uint4 hi, lo;
    split4(v1, hi.x, hi.y, lo.x, lo.y);
    split4(v2, hi.z, hi.w, lo.z, lo.w);
    size_t off = tiled_off(tile, stage, row, chunk);
    *(uint4*)((char*)h + off) = hi;
    *(uint4*)((char*)l + off) = lo;
}

// gather emb rows (A row m = t*8+b -> token x[b*T+t]) -> tiled planes
__global__ void cvt_gather_tiled_k(const float* __restrict__ emb,
                                   const int* __restrict__ tok,
                                   __nv_bfloat16* __restrict__ h,
                                   __nv_bfloat16* __restrict__ l,
                                   unsigned* __restrict__ bar) {
    if (blockIdx.x == 0 && threadIdx.x == 0) { bar[0] = 0u; bar[32] = 0u; }
    int i = blockIdx.x * blockDim.x + threadIdx.x;
    int chunk = i & 7;
    int row   = (i >> 3) & 127;
    int stage = (i >> 10) & 15;
    int tile  = i >> 14;
    int m     = tile * 128 + row;
    int tk = __ldg(&tok[(m & 7) * T_ + (m >> 3)]);
    int k  = stage * 64 + chunk * 8;
    const float4* s4 = (const float4*)(emb + (size_t)tk * S_ + k);
    float4 v1 = __ldg(s4), v2 = __ldg(s4 + 1);
    uint4 hi, lo;
    split4(v1, hi.x, hi.y, lo.x, lo.y);
    split4(v2, hi.z, hi.w, lo.z, lo.w);
    size_t off = tiled_off(tile, stage, row, chunk);
    *(uint4*)((char*)h + off) = hi;
    *(uint4*)((char*)l + off) = lo;
}

// ---------------- primitives ----------------------------------------------
__device__ __forceinline__ void ldsm4(unsigned& r0, unsigned& r1, unsigned& r2,
                                      unsigned& r3, unsigned addr) {
    asm volatile("ldmatrix.sync.aligned.m8n8.x4.shared.b16 {%0,%1,%2,%3}, [%4];\n"
                 : "=r"(r0), "=r"(r1), "=r"(r2), "=r"(r3) : "r"(addr));
}
__device__ __forceinline__ void ldsm2(unsigned& r0, unsigned& r1, unsigned addr) {
    asm volatile("ldmatrix.sync.aligned.m8n8.x2.shared.b16 {%0,%1}, [%2];\n"
                 : "=r"(r0), "=r"(r1) : "r"(addr));
}
__device__ __forceinline__ void mma16816(float* c, const unsigned* a, const unsigned* b) {
    asm volatile(
        "mma.sync.aligned.m16n8k16.row.col.f32.bf16.bf16.f32 "
        "{%0,%1,%2,%3}, {%4,%5,%6,%7}, {%8,%9}, {%0,%1,%2,%3};\n"
        : "+f"(c[0]), "+f"(c[1]), "+f"(c[2]), "+f"(c[3])
        : "r"(a[0]), "r"(a[1]), "r"(a[2]), "r"(a[3]), "r"(b[0]), "r"(b[1]));
}
__device__ __forceinline__ void bulkcp(unsigned dst, const void* src,
                                       unsigned bytes, unsigned mbar) {
    asm volatile(
        "cp.async.bulk.shared::cluster.global.mbarrier::complete_tx::bytes "
        "[%0], [%1], %2, [%3];\n"
        :: "r"(dst), "l"(src), "r"(bytes), "r"(mbar) : "memory");
}
__device__ __forceinline__ void mbar_wait(unsigned addr, unsigned parity) {
    unsigned done;
    do {
        asm volatile(
            "{\n\t.reg .pred p;\n\t"
            "mbarrier.try_wait.parity.acquire.cta.shared::cta.b64 p, [%1], %2;\n\t"
            "selp.b32 %0, 1, 0, p;\n\t}"
            : "=r"(done) : "r"(addr), "r"(parity) : "memory");
    } while (!done);
}

// ============== bulk-copy HMMA GEMM: tile 128x128, K64 stage ring =========
// Stage (64KB): AH@0 AL@16384 BH@32768 BL@49152. 3 slots + mbarriers @GEMM_CTRL.
// One elected thread per stage: expect_tx(64KB) + 4x 16KB cp.async.bulk from
// the tiled global planes. Compute identical to round-6 (8 warps, 64x32 warp
// tile, 3-term bf16-split mma).
#define GEMM_STAGE 65536u
#define GEMM_CTRL  196608u
#define GEMM_SMEM3 (196608 + 64)

__global__ void __launch_bounds__(256)
gemm_blk(int N, const __nv_bfloat16* __restrict__ Ath, const __nv_bfloat16* __restrict__ Atl,
         const __nv_bfloat16* __restrict__ Bth, const __nv_bfloat16* __restrict__ Btl,
         const float* __restrict__ bias, float* __restrict__ C, int mode)
{
    extern __shared__ char smx[];
    const unsigned sbase = (unsigned)__cvta_generic_to_shared(smx);
    const unsigned ctrl = sbase + GEMM_CTRL;
    const int tid = threadIdx.x;
    const int bx = blockIdx.x;      // m tile
    const int by = blockIdx.y;      // n tile
    const int m0 = bx * 128, n0 = by * 128;

    if (tid == 0) {
        asm volatile("mbarrier.init.shared.b64 [%0], 1;" :: "r"(ctrl)      : "memory");
        asm volatile("mbarrier.init.shared.b64 [%0], 1;" :: "r"(ctrl + 8)  : "memory");
        asm volatile("mbarrier.init.shared.b64 [%0], 1;" :: "r"(ctrl + 16) : "memory");
    }
    __syncthreads();

    const char* Abase = (const char*)Ath + (size_t)bx * (KT_ * 16384);
    const char* ALbase = (const char*)Atl + (size_t)bx * (KT_ * 16384);
    const char* Bbase = (const char*)Bth + (size_t)by * (KT_ * 16384);
    const char* BLbase = (const char*)Btl + (size_t)by * (KT_ * 16384);

    // prologue: stages 0 and 1
    if (tid == 0) {
        #pragma unroll
        for (int s = 0; s < 2; ++s) {
            unsigned mb = ctrl + (unsigned)s * 8;
            asm volatile("mbarrier.arrive.expect_tx.shared.b64 _, [%0], %1;"
                         :: "r"(mb), "r"(65536u) : "memory");
            unsigned slotb = sbase + (unsigned)s * GEMM_STAGE;
            bulkcp(slotb,          Abase  + s * 16384, 16384u, mb);
            bulkcp(slotb + 16384u, ALbase + s * 16384, 16384u, mb);
            bulkcp(slotb + 32768u, Bbase  + s * 16384, 16384u, mb);
            bulkcp(slotb + 49152u, BLbase + s * 16384, 16384u, mb);
        }
    }

    // ---- compute coords (round-6 layout) ----
    const int wid = tid >> 5, lane = tid & 31;
    const int warp_m = wid >> 2, warp_n = wid & 3;
    const int m_base = warp_m * 64, n_base = warp_n * 32;
    const unsigned aswz = (unsigned)(lane & 7) * 16u;
    const unsigned arow = (unsigned)(m_base + (lane & 7) + ((lane >> 3) & 1) * 8);
    const unsigned acol = (unsigned)(lane >> 4);
    const unsigned brow = (unsigned)(n_base + (lane & 7) + ((lane >> 4) & 1) * 8);
    const unsigned bcol = (unsigned)((lane >> 3) & 1);

    float acc[4][4][4];
    #pragma unroll
    for (int i = 0; i < 4; ++i)
        #pragma unroll
        for (int j = 0; j < 4; ++j)
            #pragma unroll
            for (int k = 0; k < 4; ++k) acc[i][j][k] = 0.f;

    for (int kt = 0; kt < KT_; ++kt) {
        mbar_wait(ctrl + (unsigned)(kt % 3) * 8, (unsigned)((kt / 3) & 1));

        const unsigned sb = sbase + (unsigned)(kt % 3) * GEMM_STAGE;

        #pragma unroll
        for (int kc = 0; kc < 4; ++kc) {
            unsigned ah[4][4], al[4][4], bh[4][2], bl[4][2];
            const unsigned ac = ((2u * kc + acol) * 16u) ^ aswz;
            const unsigned bc = ((2u * kc + bcol) * 16u) ^ aswz;
            #pragma unroll
            for (int p = 0; p < 2; ++p) {
                unsigned addr = sb + 32768u + (brow + p * 16u) * 128u + bc;
                ldsm4(bh[2*p][0], bh[2*p][1], bh[2*p+1][0], bh[2*p+1][1], addr);
                ldsm4(bl[2*p][0], bl[2*p][1], bl[2*p+1][0], bl[2*p+1][1], addr + 16384u);
            }
            #pragma unroll
            for (int fm = 0; fm < 4; ++fm) {
                unsigned addr = sb + (arow + fm * 16u) * 128u + ac;
                ldsm4(ah[fm][0], ah[fm][1], ah[fm][2], ah[fm][3], addr);
                ldsm4(al[fm][0], al[fm][1], al[fm][2], al[fm][3], addr + 16384u);
            }
            #pragma unroll
            for (int fm = 0; fm < 4; ++fm)
                #pragma unroll
                for (int fn = 0; fn < 4; ++fn)
                    mma16816(acc[fm][fn], ah[fm], bh[fn]);
            #pragma unroll
            for (int fm = 0; fm < 4; ++fm)
                #pragma unroll
                for (int fn = 0; fn < 4; ++fn)
                    mma16816(acc[fm][fn], ah[fm], bl[fn]);
            #pragma unroll
            for (int fm = 0; fm < 4; ++fm)
                #pragma unroll
                for (int fn = 0; fn < 4; ++fn)
                    mma16816(acc[fm][fn], al[fm], bh[fn]);
        }
        __syncthreads();   // all warps done reading slot (kt-1)'s successor reuse

        if (tid == 0 && kt + 2 < KT_) {
            int s = kt + 2;
            unsigned mb = ctrl + (unsigned)(s % 3) * 8;
            asm volatile("mbarrier.arrive.expect_tx.shared.b64 _, [%0], %1;"
                         :: "r"(mb), "r"(65536u) : "memory");
            unsigned slotb = sbase + (unsigned)(s % 3) * GEMM_STAGE;
            bulkcp(slotb,          Abase  + s * 16384, 16384u, mb);
            bulkcp(slotb + 16384u, ALbase + s * 16384, 16384u, mb);
            bulkcp(slotb + 32768u, Bbase  + s * 16384, 16384u, mb);
            bulkcp(slotb + 49152u, BLbase + s * 16384, 16384u, mb);
        }
    }

    // ---- epilogue ----
    const int g = lane >> 2, q = lane & 3;
    #pragma unroll
    for (int fm = 0; fm < 4; ++fm) {
        int row0 = m0 + m_base + fm * 16 + g;
        int row1 = row0 + 8;
        float *p0, *p1;
        if (mode == 0) {
            p0 = C + (size_t)row0 * N;
            p1 = C + (size_t)row1 * N;
        } else {
            p0 = C + (size_t)(row0 & 7) * ((size_t)T_ * V_) + (size_t)(row0 >> 3) * V_;
            p1 = C + (size_t)(row1 & 7) * ((size_t)T_ * V_) + (size_t)(row1 >> 3) * V_;
        }
        #pragma unroll
        for (int fn = 0; fn < 4; ++fn) {
            int col = n0 + n_base + fn * 8 + q * 2;
            float b0 = 0.f, b1 = 0.f;
            if (bias) { b0 = __ldg(&bias[col]); b1 = __ldg(&bias[col + 1]); }
            float2 v0 = make_float2(acc[fm][fn][0] + b0, acc[fm][fn][1] + b1);
            float2 v1 = make_float2(acc[fm][fn][2] + b0, acc[fm][fn][3] + b1);
            *(float2*)(p0 + col) = v0;
            *(float2*)(p1 + col) = v1;
        }
    }
}

// ---------------- persistent recurrence (round-12 best, verbatim) ---------
#define WHH_OFF 0u
#define WHL_OFF 65536u
#define HH_OFF  131072u
#define HL_OFF  147456u
#define PART_OFF 163840u
#define FP_OFF   172032u
#define REC_BYTES (172032 + 544 * 4)

__device__ __forceinline__ void grid_barrier(unsigned* bar) {
    __syncthreads();
    if (threadIdx.x == 0) {
        unsigned g;
        asm volatile("ld.acquire.gpu.global.u32 %0, [%1];" : "=r"(g) : "l"(bar + 32));
        unsigned old;
        asm volatile("atom.release.gpu.global.add.u32 %0, [%1], %2;"
                     : "=r"(old) : "l"(bar), "r"(1u));
        if (old == GRID_REC - 1) {
            asm volatile("st.relaxed.gpu.global.u32 [%0], %1;" :: "l"(bar), "r"(0u));
            asm volatile("red.release.gpu.global.add.u32 [%0], %1;" :: "l"(bar + 32), "r"(1u));
        } else {
            unsigned cur2;
            asm volatile("ld.acquire.gpu.global.u32 %0, [%1];" : "=r"(cur2) : "l"(bar + 32));
            while (cur2 == g) {
                asm volatile("nanosleep.u32 64;");
                asm volatile("ld.acquire.gpu.global.u32 %0, [%1];" : "=r"(cur2) : "l"(bar + 32));
            }
        }
    }
    __syncthreads();
}

__device__ __forceinline__ float sigmf(float x) { return 1.f / (1.f + expf(-x)); }

__global__ void __launch_bounds__(256, 1)
lstm_rec(const float* __restrict__ xproj,
         const float* __restrict__ Wh,
         const float* __restrict__ gamma, const float* __restrict__ beta,
         float* __restrict__ H,
         float* __restrict__ hfin, float* __restrict__ cfin,
         float* __restrict__ red, unsigned* __restrict__ bar)
{
    extern __shared__ char smem[];
    const unsigned sb = (unsigned)__cvta_generic_to_shared(smem);
    float* fp     = (float*)(smem + FP_OFF);
    float* gbuf   = fp;
    float* craw   = fp + 256;
    float* hbuf   = fp + 320;
    float* gmb    = fp + 384;
    float* stat   = fp + 400;
    float* lnpart = fp + 416;
    float* partf  = (float*)(smem + PART_OFF);

    const int tid = threadIdx.x;
    const int blk = blockIdx.x;
    const int s0  = blk * 8;
    const int wid = tid >> 5, lane = tid & 31;

    {
        int r = tid >> 3, s = tid & 7;
        int g = r >> 3, u = r & 7;
        const float4* src = (const float4*)(Wh + (size_t)(g * S_ + s0 + u) * S_);
        unsigned rowb = (unsigned)r * 2048u;
        unsigned sw = (unsigned)(r & 7) * 16u;
        #pragma unroll 4
        for (int jj = 0; jj < 16; ++jj) {
            int cj = s * 16 + jj;
            float4 v1 = __ldg(src + cj * 2);
            float4 v2 = __ldg(src + cj * 2 + 1);
            uint4 hi, lo;
            split4(v1, hi.x, hi.y, lo.x, lo.y);
            split4(v2, hi.z, hi.w, lo.z, lo.w);
            unsigned off = rowb + (((unsigned)cj * 16u) ^ sw);
            *(uint4*)(smem + WHH_OFF + off) = hi;
            *(uint4*)(smem + WHL_OFF + off) = lo;
        }
    }
    if (tid < 8)  { gmb[tid] = __ldg(&gamma[s0 + tid]); gmb[8 + tid] = __ldg(&beta[s0 + tid]); }
    gbuf[tid] = 0.f;
    __syncthreads();

    const int uu = tid >> 3, bb = tid & 7;

    const unsigned arl = (unsigned)((lane & 7) + ((lane >> 3) & 1) * 8);
    const unsigned asw = (unsigned)(lane & 7) * 16u;
    const unsigned akh = (unsigned)(lane >> 4) * 16u;
    const unsigned brl = (unsigned)(lane & 7);
    const unsigned bkh = (unsigned)((lane >> 3) & 1) * 16u;
    const unsigned bsw = brl * 16u;

    for (int t = 0; t < T_; ++t) {
        float xpi = 0.f, xpf = 0.f, xpo = 0.f, xpg = 0.f;
        if (tid < 64) {
            const float* xp = xproj + (size_t)(t * B_ + bb) * GS_ + s0 + uu;
            xpi = __ldg(xp + 0 * S_); xpf = __ldg(xp + 1 * S_);
            xpo = __ldg(xp + 2 * S_); xpg = __ldg(xp + 3 * S_);
        }

        if (t > 0) {
            {
                const float* Hrow = H + (size_t)(t - 1) * (B_ * S_) + (size_t)wid * S_;
                unsigned rowb = (unsigned)wid * 2048u;
                unsigned sw = (unsigned)wid * 16u;
                #pragma unroll
                for (int j = 0; j < 4; ++j) {
                    float4 v1 = __ldcg((const float4*)(Hrow + j * 256 + lane * 8));
                    float4 v2 = __ldcg((const float4*)(Hrow + j * 256 + lane * 8 + 4));
                    uint4 hi, lo;
                    split4(v1, hi.x, hi.y, lo.x, lo.y);
                    split4(v2, hi.z, hi.w, lo.z, lo.w);
                    unsigned off = rowb + ((((unsigned)(lane + j * 32)) * 16u) ^ sw);
                    *(uint4*)(smem + HH_OFF + off) = hi;
                    *(uint4*)(smem + HL_OFF + off) = lo;
                }
            }
            if (tid < 64) {
                int par = (t - 1) & 1;
                const float* rp = red + (size_t)par * B_ * GRID_REC * 2;
                int b = tid >> 3, seg = tid & 7;
                float s1 = 0.f, s2 = 0.f;
                #pragma unroll
                for (int q = 0; q < 16; ++q) {
                    float2 v = __ldcg((const float2*)(rp + ((size_t)b * GRID_REC + seg * 16 + q) * 2));
                    s1 += v.x; s2 += v.y;
                }
                lnpart[tid * 2] = s1; lnpart[tid * 2 + 1] = s2;
            }
            __syncthreads();

            if (tid < 8) {
                float s1 = 0.f, s2 = 0.f;
                #pragma unroll
                for (int seg = 0; seg < 8; ++seg) {
                    s1 += lnpart[(tid * 8 + seg) * 2];
                    s2 += lnpart[(tid * 8 + seg) * 2 + 1];
                }
                float mu = s1 * (1.f / (float)S_);
                float var = s2 * (1.f / (float)S_) - mu * mu;
                stat[tid] = mu; stat[8 + tid] = rsqrtf(var + EPS_);
            }

            float acc[2][4];
            #pragma unroll
            for (int mt = 0; mt < 2; ++mt)
                #pragma unroll
                for (int r = 0; r < 4; ++r) acc[mt][r] = 0.f;

            #pragma unroll
            for (int i = 0; i < 8; ++i) {
                unsigned c32 = (unsigned)(wid + i * 8) * 32u;
                unsigned bh[2], bl[2];
                unsigned boff = brl * 2048u + ((c32 + bkh) ^ bsw);
                ldsm2(bh[0], bh[1], sb + HH_OFF + boff);
                ldsm2(bl[0], bl[1], sb + HL_OFF + boff);
                unsigned ah0[4], al0[4], ah1[4], al1[4];
                unsigned ak = (c32 + akh) ^ asw;
                unsigned a0 = arl * 2048u + ak;
                unsigned a1 = (arl + 16u) * 2048u + ak;
                ldsm4(ah0[0], ah0[1], ah0[2], ah0[3], sb + WHH_OFF + a0);
                ldsm4(al0[0], al0[1], al0[2], al0[3], sb + WHL_OFF + a0);
                ldsm4(ah1[0], ah1[1], ah1[2], ah1[3], sb + WHH_OFF + a1);
                ldsm4(al1[0], al1[1], al1[2], al1[3], sb + WHL_OFF + a1);
                mma16816(acc[0], ah0, bh);
                mma16816(acc[1], ah1, bh);
                mma16816(acc[0], ah0, bl);
                mma16816(acc[1], ah1, bl);
                mma16816(acc[0], al0, bh);
                mma16816(acc[1], al1, bh);
            }
            #pragma unroll
            for (int mt = 0; mt < 2; ++mt) {
                float4* pd = (float4*)partf + (wid * 2 + mt) * 32 + lane;
                *pd = make_float4(acc[mt][0], acc[mt][1], acc[mt][2], acc[mt][3]);
            }
            __syncthreads();

            {
                int col = tid >> 3, b = tid & 7;
                int mt = col >> 4, rr = col & 15;
                int g = rr & 7, half = rr >> 3;
                int reg = half * 2 + (b & 1);
                int ln = g * 4 + (b >> 1);
                float v = 0.f;
                #pragma unroll
                for (int w2 = 0; w2 < 8; ++w2)
                    v += partf[(w2 * 2 + mt) * 128 + ln * 4 + reg];
                gbuf[tid] = v;
            }
            __syncthreads();
        }

        if (tid < 64) {
            float cn = 0.f;
            if (t > 0)
                cn = (craw[tid] - stat[bb]) * stat[8 + bb] * gmb[uu] + gmb[8 + uu];
            float pi = xpi + gbuf[(0 * 8 + uu) * 8 + bb];
            float pf = xpf + gbuf[(1 * 8 + uu) * 8 + bb];
            float po = xpo + gbuf[(2 * 8 + uu) * 8 + bb];
            float pg = xpg + gbuf[(3 * 8 + uu) * 8 + bb];
            float ig = sigmf(pi), fg = sigmf(pf), og = sigmf(po), gg = tanhf(pg);
            float cr = fg * cn + ig * gg;
            float hh = og * tanhf(cr);
            craw[tid] = cr;
            hbuf[tid] = hh;
            H[(size_t)t * (B_ * S_) + bb * S_ + s0 + uu] = hh;
        }
        __syncthreads();

        if (tid < 8) {
            float s1 = 0.f, s2 = 0.f;
            #pragma unroll
            for (int u = 0; u < 8; ++u) { float v = craw[u * 8 + tid]; s1 += v; s2 += v * v; }
            float2* rp = (float2*)(red + ((size_t)(t & 1) * B_ + tid) * (GRID_REC * 2) + blk * 2);
            *rp = make_float2(s1, s2);
        }

        grid_barrier(bar);
    }

    {
        int par = (T_ - 1) & 1;
        const float* rp = red + (size_t)par * B_ * GRID_REC * 2;
        if (tid < 64) {
            int b = tid >> 3, seg = tid & 7;
            float s1 = 0.f, s2 = 0.f;
            #pragma unroll
            for (int q = 0; q < 16; ++q) {
                float2 v = __ldcg((const float2*)(rp + ((size_t)b * GRID_REC + seg * 16 + q) * 2));
                s1 += v.x; s2 += v.y;
            }
            lnpart[tid * 2] = s1; lnpart[tid * 2 + 1] = s2;
        }
        __syncthreads();
        if (tid < 8) {
            float s1 = 0.f, s2 = 0.f;
            #pragma unroll
            for (int seg = 0; seg < 8; ++seg) {
                s1 += lnpart[(tid * 8 + seg) * 2];
                s2 += lnpart[(tid * 8 + seg) * 2 + 1];
            }
            float mu = s1 * (1.f / (float)S_);
            float var = s2 * (1.f / (float)S_) - mu * mu;
            stat[tid] = mu; stat[8 + tid] = rsqrtf(var + EPS_);
        }
        __syncthreads();
        if (tid < 64) {
            float cn = (craw[tid] - stat[bb]) * stat[8 + bb] * gmb[uu] + gmb[8 + uu];
            cfin[bb * S_ + s0 + uu] = cn;
            hfin[bb * S_ + s0 + uu] = hbuf[tid];
        }
    }
}

// ---------------- host launcher -------------------------------------------
extern "C" void kernel_launch(void* const* d_in, const int* in_sizes, int n_in,
                              void* d_out, int out_size)
{
    (void)in_sizes; (void)n_in; (void)out_size;
    const int*   x     = (const int*)d_in[0];
    const float* emb   = (const float*)d_in[1];
    const float* Wx    = (const float*)d_in[2];
    const float* Wh    = (const float*)d_in[3];
    const float* gamma = (const float*)d_in[4];
    const float* beta  = (const float*)d_in[5];
    const float* Wout  = (const float*)d_in[6];
    const float* bout  = (const float*)d_in[7];
    float* out = (float*)d_out;

    float *xproj, *H0, *H1, *red;
    unsigned* bar;
    __nv_bfloat16 *Wxh, *Wxl, *Wouth, *Woutl, *Ah, *Al;
    cudaGetSymbolAddress((void**)&xproj, d_xproj);
    cudaGetSymbolAddress((void**)&H0,    d_H0);
    cudaGetSymbolAddress((void**)&H1,    d_H1);
    cudaGetSymbolAddress((void**)&red,   d_red);
    cudaGetSymbolAddress((void**)&bar,   d_bar);
    cudaGetSymbolAddress((void**)&Wxh,   d_Wxh);
    cudaGetSymbolAddress((void**)&Wxl,   d_Wxl);
    cudaGetSymbolAddress((void**)&Wouth, d_Wouth);
    cudaGetSymbolAddress((void**)&Woutl, d_Woutl);
    cudaGetSymbolAddress((void**)&Ah,    d_Ah);
    cudaGetSymbolAddress((void**)&Al,    d_Al);

    cudaFuncSetAttribute(lstm_rec, cudaFuncAttributeMaxDynamicSharedMemorySize, REC_BYTES);
    cudaFuncSetAttribute(gemm_blk, cudaFuncAttributeMaxDynamicSharedMemorySize, GEMM_SMEM3);

    float* h_out = out + (size_t)B_ * T_ * V_;
    float* c_out = h_out + (size_t)L_ * B_ * S_;

    const size_t wstride = (size_t)GS_ * S_;

    // splits into TILED layouts
    cvt_gather_tiled_k<<<(T_ * B_ * S_ / 8 + 255) / 256, 256>>>(emb, x, Ah, Al, bar);
    cvt_tiled_k<<<(GS_ * S_ / 8 + 255) / 256, 256>>>(Wx, Wxh, Wxl, GS_ * S_ / 8);
    cvt_tiled_k<<<(GS_ * S_ / 8 + 255) / 256, 256>>>(Wx + wstride, Wxh + wstride, Wxl + wstride, GS_ * S_ / 8);
    cvt_tiled_k<<<(V_ * S_ / 8 + 255) / 256, 256>>>(Wout, Wouth, Woutl, V_ * S_ / 8);

    // layer 0
    gemm_blk<<<dim3((T_ * B_) / 128, GS_ / 128), 256, GEMM_SMEM3>>>(
        GS_, Ah, Al, Wxh, Wxl, nullptr, xproj, 0);
    lstm_rec<<<GRID_REC, 256, REC_BYTES>>>(
        xproj, Wh, gamma, beta, H0, h_out, c_out, red, bar);
    // layer 1
    cvt_tiled_k<<<(T_ * B_ * S_ / 8 + 255) / 256, 256>>>(H0, Ah, Al, T_ * B_ * S_ / 8);
    gemm_blk<<<dim3((T_ * B_) / 128, GS_ / 128), 256, GEMM_SMEM3>>>(
        GS_, Ah, Al, Wxh + wstride, Wxl + wstride, nullptr, xproj, 0);
    lstm_rec<<<GRID_REC, 256, REC_BYTES>>>(
        xproj, Wh + wstride, gamma + S_, beta + S_, H1,
        h_out + (size_t)B_ * S_, c_out + (size_t)B_ * S_, red, bar);
    // logits
    cvt_tiled_k<<<(T_ * B_ * S_ / 8 + 255) / 256, 256>>>(H1, Ah, Al, T_ * B_ * S_ / 8);
    gemm_blk<<<dim3((T_ * B_) / 128, V_ / 128), 256, GEMM_SMEM3>>>(
        V_, Ah, Al, Wouth, Woutl, bout, out, 1);
}